// round 2
// baseline (speedup 1.0000x reference)
#include <cuda_runtime.h>
#include <cstdint>

// ---------------- problem constants ----------------
#define BW    1024
#define SEQ   144
#define CH    512
#define NH    16
#define DH    32
#define NWIN  64
#define MROWS (BW*SEQ)          // 147456
#define LOG100 4.6051701859880913680f

// ---------------- scratch (device globals; no cudaMalloc allowed) ----------
__device__ float g_qkv[(size_t)MROWS * 1536];   // q|k|v concatenated per row
__device__ float g_att[(size_t)MROWS * 512];    // attention output (Bw,L,C)

__device__ __forceinline__ uint32_t f2tf32(float f) {
    uint32_t u;
    asm("cvt.rna.tf32.f32 %0, %1;" : "=r"(u) : "f"(f));
    return u;
}

// permutation within each 8-wide k-group so that (k=tg, k=tg+4) are adjacent
__device__ __forceinline__ int perm8(int k) { return ((k & 3) << 1) | (k >> 2); }

__device__ __forceinline__ void mma8(float* c, const uint32_t* a, uint32_t b0, uint32_t b1) {
    asm volatile(
        "mma.sync.aligned.m16n8k8.row.col.f32.tf32.tf32.f32 "
        "{%0,%1,%2,%3}, {%4,%5,%6,%7}, {%8,%9}, {%0,%1,%2,%3};\n"
        : "+f"(c[0]), "+f"(c[1]), "+f"(c[2]), "+f"(c[3])
        : "r"(a[0]), "r"(a[1]), "r"(a[2]), "r"(a[3]), "r"(b0), "r"(b1));
}

// ============================================================
// GEMM: C[m, z*512 + n] = sum_k A[m,k] * B_z[n,k] + bias_z[n]
// tf32 mma.sync m16n8k8, tiles 128x128x32, 256 threads (8 warps, 2x4)
// SMEM k-groups stored permuted -> all fragment loads are LDS.64
// ============================================================
#define APAD 36   // smem row stride in 4B words

__device__ __forceinline__ void gemm_lds_tiles(const float* __restrict__ Ap,
                                               const float* __restrict__ Bp,
                                               int tid, int K,
                                               float4* a_st, float4* b_st) {
#pragma unroll
    for (int i = 0; i < 4; i++) {
        int idx = tid + i * 256;
        int r = idx >> 3, c = (idx & 7) * 4;
        a_st[i] = *(const float4*)(Ap + (size_t)r * K + c);
        b_st[i] = *(const float4*)(Bp + (size_t)r * K + c);
    }
}

__device__ __forceinline__ void gemm_sts_tiles(uint32_t* __restrict__ As,
                                               uint32_t* __restrict__ Bs,
                                               int tid,
                                               const float4* a_st, const float4* b_st) {
#pragma unroll
    for (int i = 0; i < 4; i++) {
        int idx = tid + i * 256;
        int r = idx >> 3, c = (idx & 7) * 4;
        // permuted positions: k-in-group c&7 in {0,4}; perm = 2*j + ((c>>2)&1)
        int base = r * APAD + (c & ~7) + ((c >> 2) & 1);
        uint32_t* da = As + base;
        da[0] = f2tf32(a_st[i].x); da[2] = f2tf32(a_st[i].y);
        da[4] = f2tf32(a_st[i].z); da[6] = f2tf32(a_st[i].w);
        uint32_t* db = Bs + base;
        db[0] = f2tf32(b_st[i].x); db[2] = f2tf32(b_st[i].y);
        db[4] = f2tf32(b_st[i].z); db[6] = f2tf32(b_st[i].w);
    }
}

__global__ void __launch_bounds__(256, 2)
gemm_tf32_kernel(const float* __restrict__ A,
                 const float* __restrict__ B0, const float* __restrict__ B1,
                 const float* __restrict__ B2,
                 const float* __restrict__ bias0, const float* __restrict__ bias1,
                 const float* __restrict__ bias2,
                 float* __restrict__ Cout, int ldc, int K)
{
    const int z  = blockIdx.x >> 2;
    const int nb = blockIdx.x & 3;
    const float* B    = (z == 0) ? B0 : (z == 1 ? B1 : B2);
    const float* bias = (z == 0) ? bias0 : (z == 1 ? bias1 : bias2);

    const int m0 = blockIdx.y * 128;
    const int n0 = nb * 128;

    extern __shared__ uint32_t smem_u[];
    uint32_t* As = smem_u;                       // [2][128][APAD]
    uint32_t* Bs = smem_u + 2 * 128 * APAD;      // [2][128][APAD]

    const int tid  = threadIdx.x;
    const int warp = tid >> 5, lane = tid & 31;
    const int wm = warp & 1;        // 0..1 -> 64 rows
    const int wn = warp >> 1;       // 0..3 -> 32 cols
    const int g  = lane >> 2, tg = lane & 3;

    float acc[4][4][4];
#pragma unroll
    for (int i = 0; i < 4; i++)
#pragma unroll
        for (int j = 0; j < 4; j++)
#pragma unroll
            for (int r = 0; r < 4; r++) acc[i][j][r] = 0.f;

    float4 a_st[4], b_st[4];
    gemm_lds_tiles(A + (size_t)m0 * K, B + (size_t)n0 * K, tid, K, a_st, b_st);
    gemm_sts_tiles(As, Bs, tid, a_st, b_st);
    __syncthreads();

    const int nk = K / 32;
    int buf = 0;
#pragma unroll 1
    for (int kt = 0; kt < nk; kt++) {
        if (kt + 1 < nk) {
            gemm_lds_tiles(A + (size_t)m0 * K + (kt + 1) * 32,
                           B + (size_t)n0 * K + (kt + 1) * 32, tid, K, a_st, b_st);
        }
        const uint32_t* Ab = As + buf * 128 * APAD;
        const uint32_t* Bb = Bs + buf * 128 * APAD;
#pragma unroll
        for (int ks = 0; ks < 4; ks++) {
            uint32_t af[4][4], bf[4][2];
#pragma unroll
            for (int mi = 0; mi < 4; mi++) {
                const uint32_t* p = Ab + (wm * 64 + mi * 16 + g) * APAD + ks * 8 + 2 * tg;
                uint2 lo = *(const uint2*)p;
                uint2 hi = *(const uint2*)(p + 8 * APAD);
                af[mi][0] = lo.x; af[mi][2] = lo.y;
                af[mi][1] = hi.x; af[mi][3] = hi.y;
            }
#pragma unroll
            for (int ni = 0; ni < 4; ni++) {
                const uint32_t* p = Bb + (wn * 32 + ni * 8 + g) * APAD + ks * 8 + 2 * tg;
                uint2 bb = *(const uint2*)p;
                bf[ni][0] = bb.x; bf[ni][1] = bb.y;
            }
#pragma unroll
            for (int mi = 0; mi < 4; mi++)
#pragma unroll
                for (int ni = 0; ni < 4; ni++)
                    mma8(acc[mi][ni], af[mi], bf[ni][0], bf[ni][1]);
        }
        if (kt + 1 < nk)
            gemm_sts_tiles(As + (buf ^ 1) * 128 * APAD, Bs + (buf ^ 1) * 128 * APAD,
                           tid, a_st, b_st);
        buf ^= 1;
        __syncthreads();
    }

    // epilogue: c0 (g,2tg) c1 (g,2tg+1) c2 (g+8,2tg) c3 (g+8,2tg+1)
#pragma unroll
    for (int mi = 0; mi < 4; mi++) {
        int row = m0 + wm * 64 + mi * 16 + g;
#pragma unroll
        for (int ni = 0; ni < 4; ni++) {
            int ncol = n0 + wn * 32 + ni * 8 + 2 * tg;
            int gcol = z * 512 + ncol;
            float b0 = bias[ncol], b1 = bias[ncol + 1];
            float2 v0 = make_float2(acc[mi][ni][0] + b0, acc[mi][ni][1] + b1);
            float2 v1 = make_float2(acc[mi][ni][2] + b0, acc[mi][ni][3] + b1);
            *(float2*)(Cout + (size_t)row * ldc + gcol) = v0;
            *(float2*)(Cout + (size_t)(row + 8) * ldc + gcol) = v1;
        }
    }
}

// ============================================================
// Attention via tensor cores. One CTA per (b,h), 9 warps.
// Warp w owns q-rows [16w,16w+16). S = QK^T by 3-term tf32 split
// (error ~1e-7 on logits), softmax exact in fp32, O = PV single tf32.
// All SMEM tiles use paired-k permuted layout -> LDS.64 fragments.
// ============================================================
#define KP 36
#define VP 148
#define PP 148
// words: ksh/ksl 2*144*36  vsm 32*148  qsh/qsl 2*9*16*36  psm 9*16*148
#define ATT_SMEM_WORDS (2*144*KP + 32*VP + 2*9*16*KP + 9*16*PP)

__global__ void __launch_bounds__(288, 1)
attn_kernel(const float* __restrict__ mask,
            const float* __restrict__ logit_scale,
            float* __restrict__ attout)
{
    const int bh = blockIdx.x;
    const int b = bh >> 4;
    const int h = bh & 15;
    const int win = b & (NWIN - 1);

    const int tid = threadIdx.x;
    const int w = tid >> 5, lane = tid & 31;
    const int g = lane >> 2, tg = lane & 3;

    extern __shared__ uint32_t sm_u[];
    uint32_t* ksh = sm_u;                    // [144][KP]
    uint32_t* ksl = ksh + 144 * KP;          // [144][KP]
    uint32_t* vsm = ksl + 144 * KP;          // [32][VP]  (V^T, tf32)
    uint32_t* qsh = vsm + 32 * VP;           // [9*16][KP]
    uint32_t* qsl = qsh + 9 * 16 * KP;       // [9*16][KP]
    uint32_t* psm = qsl + 9 * 16 * KP;       // [9*16][PP] (P, tf32)

    const float scale = expf(fminf(logit_scale[h], LOG100));

    const float* qbase = g_qkv + (size_t)(b * SEQ) * 1536 + h * 32;
    const float* kbase = qbase + 512;
    const float* vbase = qbase + 1024;

    // ---- load K (normalized, hi/lo split) and V^T (tf32), 2 threads/row ----
    {
        int r = tid >> 1, half = tid & 1;
        const float4* kr = (const float4*)(kbase + (size_t)r * 1536 + half * 16);
        float kv[16];
        float sq = 0.f;
#pragma unroll
        for (int i4 = 0; i4 < 4; i4++) {
            float4 f = kr[i4];
            kv[i4*4+0] = f.x; kv[i4*4+1] = f.y; kv[i4*4+2] = f.z; kv[i4*4+3] = f.w;
            sq += f.x*f.x + f.y*f.y + f.z*f.z + f.w*f.w;
        }
        sq += __shfl_xor_sync(0xffffffffu, sq, 1);
        float inv = 1.f / fmaxf(sqrtf(sq), 1e-12f);
#pragma unroll
        for (int i = 0; i < 16; i++) {
            int d = half * 16 + i;
            float f = kv[i] * inv;
            uint32_t hi = f2tf32(f);
            float lo = f - __uint_as_float(hi);
            int pos = r * KP + (d & ~7) + perm8(d & 7);
            ksh[pos] = hi;
            ksl[pos] = f2tf32(lo);
        }
        // V^T: row d, col r (permuted in 8-groups of r)
        const float4* vr = (const float4*)(vbase + (size_t)r * 1536 + half * 16);
        int cperm = (r & ~7) + perm8(r & 7);
#pragma unroll
        for (int i4 = 0; i4 < 4; i4++) {
            float4 f = vr[i4];
            int d = half * 16 + i4 * 4;
            vsm[(d + 0) * VP + cperm] = f2tf32(f.x);
            vsm[(d + 1) * VP + cperm] = f2tf32(f.y);
            vsm[(d + 2) * VP + cperm] = f2tf32(f.z);
            vsm[(d + 3) * VP + cperm] = f2tf32(f.w);
        }
    }

    // ---- load Q rows for this warp (normalized, scaled, hi/lo split) ----
#pragma unroll
    for (int rr = 0; rr < 16; rr++) {
        int row = w * 16 + rr;
        float qv = qbase[(size_t)row * 1536 + lane];
        float sq = qv * qv;
#pragma unroll
        for (int off = 16; off > 0; off >>= 1)
            sq += __shfl_xor_sync(0xffffffffu, sq, off);
        float inv = scale / fmaxf(sqrtf(sq), 1e-12f);
        float f = qv * inv;
        uint32_t hi = f2tf32(f);
        float lo = f - __uint_as_float(hi);
        int pos = row * KP + (lane & ~7) + perm8(lane & 7);
        qsh[pos] = hi;
        qsl[pos] = f2tf32(lo);
    }
    __syncthreads();

    // ---- A fragments (Q) for all 4 k-tiles, hi & lo ----
    uint32_t ah[4][4], al[4][4];
#pragma unroll
    for (int kt = 0; kt < 4; kt++) {
        const uint32_t* p = qsh + (w * 16 + g) * KP + kt * 8 + 2 * tg;
        uint2 lo = *(const uint2*)p;
        uint2 hi = *(const uint2*)(p + 8 * KP);
        ah[kt][0] = lo.x; ah[kt][2] = lo.y; ah[kt][1] = hi.x; ah[kt][3] = hi.y;
        const uint32_t* q = qsl + (w * 16 + g) * KP + kt * 8 + 2 * tg;
        uint2 lo2 = *(const uint2*)q;
        uint2 hi2 = *(const uint2*)(q + 8 * KP);
        al[kt][0] = lo2.x; al[kt][2] = lo2.y; al[kt][1] = hi2.x; al[kt][3] = hi2.y;
    }

    // ---- S = Qn @ Kn^T (3-term tf32 split) ----
    float acc[18][4];
#pragma unroll
    for (int nt = 0; nt < 18; nt++)
#pragma unroll
        for (int r = 0; r < 4; r++) acc[nt][r] = 0.f;

#pragma unroll
    for (int nt = 0; nt < 18; nt++) {
#pragma unroll
        for (int kt = 0; kt < 4; kt++) {
            int off = (nt * 8 + g) * KP + kt * 8 + 2 * tg;
            uint2 bh = *(const uint2*)(ksh + off);
            uint2 bl = *(const uint2*)(ksl + off);
            mma8(acc[nt], ah[kt], bh.x, bh.y);
            mma8(acc[nt], al[kt], bh.x, bh.y);
            mma8(acc[nt], ah[kt], bl.x, bl.y);
        }
    }

    // ---- add mask, softmax (exact, fp32) ----
    const float* mrow = mask + (size_t)win * SEQ * SEQ;
    const float NEG_INF = __int_as_float(0xff800000);
    float mx0 = NEG_INF, mx1 = NEG_INF;
#pragma unroll
    for (int nt = 0; nt < 18; nt++) {
        float2 m0 = *(const float2*)(mrow + (size_t)(w * 16 + g) * SEQ + nt * 8 + 2 * tg);
        float2 m1 = *(const float2*)(mrow + (size_t)(w * 16 + g + 8) * SEQ + nt * 8 + 2 * tg);
        acc[nt][0] += m0.x; acc[nt][1] += m0.y;
        acc[nt][2] += m1.x; acc[nt][3] += m1.y;
        mx0 = fmaxf(mx0, fmaxf(acc[nt][0], acc[nt][1]));
        mx1 = fmaxf(mx1, fmaxf(acc[nt][2], acc[nt][3]));
    }
    mx0 = fmaxf(mx0, __shfl_xor_sync(0xffffffffu, mx0, 1));
    mx0 = fmaxf(mx0, __shfl_xor_sync(0xffffffffu, mx0, 2));
    mx1 = fmaxf(mx1, __shfl_xor_sync(0xffffffffu, mx1, 1));
    mx1 = fmaxf(mx1, __shfl_xor_sync(0xffffffffu, mx1, 2));

    float s0 = 0.f, s1 = 0.f;
#pragma unroll
    for (int nt = 0; nt < 18; nt++) {
        acc[nt][0] = __expf(acc[nt][0] - mx0); s0 += acc[nt][0];
        acc[nt][1] = __expf(acc[nt][1] - mx0); s0 += acc[nt][1];
        acc[nt][2] = __expf(acc[nt][2] - mx1); s1 += acc[nt][2];
        acc[nt][3] = __expf(acc[nt][3] - mx1); s1 += acc[nt][3];
    }
    s0 += __shfl_xor_sync(0xffffffffu, s0, 1);
    s0 += __shfl_xor_sync(0xffffffffu, s0, 2);
    s1 += __shfl_xor_sync(0xffffffffu, s1, 1);
    s1 += __shfl_xor_sync(0xffffffffu, s1, 2);
    float inv0 = 1.f / s0, inv1 = 1.f / s1;

    // ---- write P (tf32, permuted columns) ----
    const int c0p = perm8(2 * tg), c1p = perm8(2 * tg + 1);
#pragma unroll
    for (int nt = 0; nt < 18; nt++) {
        uint32_t* p0 = psm + (w * 16 + g) * PP + nt * 8;
        p0[c0p] = f2tf32(acc[nt][0] * inv0);
        p0[c1p] = f2tf32(acc[nt][1] * inv0);
        uint32_t* p1 = psm + (w * 16 + g + 8) * PP + nt * 8;
        p1[c0p] = f2tf32(acc[nt][2] * inv1);
        p1[c1p] = f2tf32(acc[nt][3] * inv1);
    }
    __syncwarp();

    // ---- O = P @ V ----
    float oc[4][4];
#pragma unroll
    for (int nt = 0; nt < 4; nt++)
#pragma unroll
        for (int r = 0; r < 4; r++) oc[nt][r] = 0.f;

#pragma unroll
    for (int kt = 0; kt < 18; kt++) {
        uint32_t a[4];
        const uint32_t* pp = psm + (w * 16 + g) * PP + kt * 8 + 2 * tg;
        uint2 lo = *(const uint2*)pp;
        uint2 hi = *(const uint2*)(pp + 8 * PP);
        a[0] = lo.x; a[2] = lo.y; a[1] = hi.x; a[3] = hi.y;
#pragma unroll
        for (int nt = 0; nt < 4; nt++) {
            uint2 bb = *(const uint2*)(vsm + (nt * 8 + g) * VP + kt * 8 + 2 * tg);
            mma8(oc[nt], a, bb.x, bb.y);
        }
    }

    // ---- store O ----
    const int row0 = b * SEQ + w * 16 + g;
#pragma unroll
    for (int nt = 0; nt < 4; nt++) {
        int col = h * 32 + nt * 8 + 2 * tg;
        *(float2*)(attout + (size_t)row0 * 512 + col)       = make_float2(oc[nt][0], oc[nt][1]);
        *(float2*)(attout + (size_t)(row0 + 8) * 512 + col) = make_float2(oc[nt][2], oc[nt][3]);
    }
}

// ============================================================
// launch
// ============================================================
extern "C" void kernel_launch(void* const* d_in, const int* in_sizes, int n_in,
                              void* d_out, int out_size)
{
    (void)in_sizes; (void)n_in; (void)out_size;
    const float* x    = (const float*)d_in[0];
    const float* mask = (const float*)d_in[1];
    const float* Wq   = (const float*)d_in[2];
    const float* bq   = (const float*)d_in[3];
    const float* Wk   = (const float*)d_in[4];
    const float* bk   = (const float*)d_in[5];
    const float* Wv   = (const float*)d_in[6];
    const float* bv   = (const float*)d_in[7];
    const float* Wp   = (const float*)d_in[8];
    const float* bp   = (const float*)d_in[9];
    const float* ls   = (const float*)d_in[10];
    float* out = (float*)d_out;

    void* qkv_p = nullptr;
    void* att_p = nullptr;
    cudaGetSymbolAddress(&qkv_p, g_qkv);
    cudaGetSymbolAddress(&att_p, g_att);
    float* qkv = (float*)qkv_p;
    float* att = (float*)att_p;

    const int gemm_smem = 2 * 2 * 128 * APAD * 4;          // 73728 B
    const int att_smem  = ATT_SMEM_WORDS * 4;              // 187136 B
    cudaFuncSetAttribute(gemm_tf32_kernel,
                         cudaFuncAttributeMaxDynamicSharedMemorySize, gemm_smem);
    cudaFuncSetAttribute(attn_kernel,
                         cudaFuncAttributeMaxDynamicSharedMemorySize, att_smem);

    // QKV projections (z folded into grid.x: 12 = 4 N-tiles * 3 matrices)
    dim3 gq(12, MROWS / 128, 1);
    gemm_tf32_kernel<<<gq, 256, gemm_smem>>>(x, Wq, Wk, Wv, bq, bk, bv,
                                             qkv, 1536, CH);

    // attention (tensor-core)
    attn_kernel<<<BW * NH, 288, att_smem>>>(mask, ls, att);

    // output projection
    dim3 gp(4, MROWS / 128, 1);
    gemm_tf32_kernel<<<gp, 256, gemm_smem>>>(att, Wp, Wp, Wp, bp, bp, bp,
                                             out, 512, CH);
}

// round 3
// speedup vs baseline: 1.5909x; 1.5909x over previous
#include <cuda_runtime.h>
#include <cstdint>

// ---------------- problem constants ----------------
#define BW    1024
#define SEQ   144
#define CH    512
#define NH    16
#define DH    32
#define NWIN  64
#define MROWS (BW*SEQ)          // 147456
#define LOG100 4.6051701859880913680f

// ---------------- scratch (device globals; no cudaMalloc allowed) ----------
__device__ float g_qkv[(size_t)MROWS * 1536];   // q|k|v concatenated per row
__device__ float g_att[(size_t)MROWS * 512];    // attention output (Bw,L,C)

__device__ __forceinline__ uint32_t f2tf32(float f) {
    uint32_t u;
    asm("cvt.rna.tf32.f32 %0, %1;" : "=r"(u) : "f"(f));
    return u;
}

__device__ __forceinline__ void mma8(float* c, const uint32_t* a, uint32_t b0, uint32_t b1) {
    asm volatile(
        "mma.sync.aligned.m16n8k8.row.col.f32.tf32.tf32.f32 "
        "{%0,%1,%2,%3}, {%4,%5,%6,%7}, {%8,%9}, {%0,%1,%2,%3};\n"
        : "+f"(c[0]), "+f"(c[1]), "+f"(c[2]), "+f"(c[3])
        : "r"(a[0]), "r"(a[1]), "r"(a[2]), "r"(a[3]), "r"(b0), "r"(b1));
}

// ============================================================
// GEMM: C[m, z*512 + n] = sum_k A[m,k] * B_z[n,k] + bias_z[n]
// tf32 mma.sync m16n8k8, tiles 128x128x32, 256 threads (8 warps, 2x4)
// Scalar conflict-free fragment loads (bank = 4g+tg), STS.128 stores.
// ============================================================
#define APAD 36   // smem row stride in 4B words

__device__ __forceinline__ void gemm_lds_tiles(const float* __restrict__ Ap,
                                               const float* __restrict__ Bp,
                                               int tid, int K,
                                               float4* a_st, float4* b_st) {
#pragma unroll
    for (int i = 0; i < 4; i++) {
        int idx = tid + i * 256;
        int r = idx >> 3, c = (idx & 7) * 4;
        a_st[i] = *(const float4*)(Ap + (size_t)r * K + c);
        b_st[i] = *(const float4*)(Bp + (size_t)r * K + c);
    }
}

__device__ __forceinline__ void gemm_sts_tiles(uint32_t* __restrict__ As,
                                               uint32_t* __restrict__ Bs,
                                               int tid,
                                               const float4* a_st, const float4* b_st) {
#pragma unroll
    for (int i = 0; i < 4; i++) {
        int idx = tid + i * 256;
        int r = idx >> 3, c = (idx & 7) * 4;
        uint4 ua = make_uint4(f2tf32(a_st[i].x), f2tf32(a_st[i].y),
                              f2tf32(a_st[i].z), f2tf32(a_st[i].w));
        *(uint4*)(As + r * APAD + c) = ua;
        uint4 ub = make_uint4(f2tf32(b_st[i].x), f2tf32(b_st[i].y),
                              f2tf32(b_st[i].z), f2tf32(b_st[i].w));
        *(uint4*)(Bs + r * APAD + c) = ub;
    }
}

__global__ void __launch_bounds__(256, 2)
gemm_tf32_kernel(const float* __restrict__ A,
                 const float* __restrict__ B0, const float* __restrict__ B1,
                 const float* __restrict__ B2,
                 const float* __restrict__ bias0, const float* __restrict__ bias1,
                 const float* __restrict__ bias2,
                 float* __restrict__ Cout, int ldc, int K)
{
    const int z  = blockIdx.x >> 2;
    const int nb = blockIdx.x & 3;
    const float* B    = (z == 0) ? B0 : (z == 1 ? B1 : B2);
    const float* bias = (z == 0) ? bias0 : (z == 1 ? bias1 : bias2);

    const int m0 = blockIdx.y * 128;
    const int n0 = nb * 128;

    extern __shared__ uint32_t smem_u[];
    uint32_t* As = smem_u;                       // [2][128][APAD]
    uint32_t* Bs = smem_u + 2 * 128 * APAD;      // [2][128][APAD]

    const int tid  = threadIdx.x;
    const int warp = tid >> 5, lane = tid & 31;
    const int wm = warp & 1;        // 0..1 -> 64 rows
    const int wn = warp >> 1;       // 0..3 -> 32 cols
    const int g  = lane >> 2, tg = lane & 3;

    float acc[4][4][4];
#pragma unroll
    for (int i = 0; i < 4; i++)
#pragma unroll
        for (int j = 0; j < 4; j++)
#pragma unroll
            for (int r = 0; r < 4; r++) acc[i][j][r] = 0.f;

    float4 a_st[4], b_st[4];
    gemm_lds_tiles(A + (size_t)m0 * K, B + (size_t)n0 * K, tid, K, a_st, b_st);
    gemm_sts_tiles(As, Bs, tid, a_st, b_st);
    __syncthreads();

    const int nk = K / 32;
    int buf = 0;
#pragma unroll 1
    for (int kt = 0; kt < nk; kt++) {
        if (kt + 1 < nk) {
            gemm_lds_tiles(A + (size_t)m0 * K + (kt + 1) * 32,
                           B + (size_t)n0 * K + (kt + 1) * 32, tid, K, a_st, b_st);
        }
        const uint32_t* Ab = As + buf * 128 * APAD;
        const uint32_t* Bb = Bs + buf * 128 * APAD;
#pragma unroll
        for (int ks = 0; ks < 4; ks++) {
            uint32_t af[4][4], bf[4][2];
#pragma unroll
            for (int mi = 0; mi < 4; mi++) {
                const uint32_t* p = Ab + (wm * 64 + mi * 16 + g) * APAD + ks * 8 + tg;
                af[mi][0] = p[0];
                af[mi][2] = p[4];
                const uint32_t* p2 = p + 8 * APAD;
                af[mi][1] = p2[0];
                af[mi][3] = p2[4];
            }
#pragma unroll
            for (int ni = 0; ni < 4; ni++) {
                const uint32_t* p = Bb + (wn * 32 + ni * 8 + g) * APAD + ks * 8 + tg;
                bf[ni][0] = p[0];
                bf[ni][1] = p[4];
            }
#pragma unroll
            for (int mi = 0; mi < 4; mi++)
#pragma unroll
                for (int ni = 0; ni < 4; ni++)
                    mma8(acc[mi][ni], af[mi], bf[ni][0], bf[ni][1]);
        }
        if (kt + 1 < nk)
            gemm_sts_tiles(As + (buf ^ 1) * 128 * APAD, Bs + (buf ^ 1) * 128 * APAD,
                           tid, a_st, b_st);
        buf ^= 1;
        __syncthreads();
    }

#pragma unroll
    for (int mi = 0; mi < 4; mi++) {
        int row = m0 + wm * 64 + mi * 16 + g;
#pragma unroll
        for (int ni = 0; ni < 4; ni++) {
            int ncol = n0 + wn * 32 + ni * 8 + 2 * tg;
            int gcol = z * 512 + ncol;
            float b0 = bias[ncol], b1 = bias[ncol + 1];
            float2 v0 = make_float2(acc[mi][ni][0] + b0, acc[mi][ni][1] + b1);
            float2 v1 = make_float2(acc[mi][ni][2] + b0, acc[mi][ni][3] + b1);
            *(float2*)(Cout + (size_t)row * ldc + gcol) = v0;
            *(float2*)(Cout + (size_t)(row + 8) * ldc + gcol) = v1;
        }
    }
}

// ============================================================
// Attention: flash-style online softmax on tensor cores.
// One CTA per (b,h), 9 warps, warp owns 16 q-rows. 24-key strips.
// S = QK^T via 3-term tf32 split; P (unnormalized exp) -> smem strip
// -> PV mma; running max/sum rescaling; divide at the end.
// K/Q stride 36, V stride 40, P-strip stride 36 (all conflict-free).
// Q smem region aliased by P strips after fragment build (1 barrier).
// ============================================================
#define KP 36
#define VP 40
#define SP 36
// words: ksh 144*36 + ksl 144*36 + vsm 144*40 + q region 2*144*36 (aliased by
//        pstrips 9*16*36 = 5184 after frag build)
#define ATT_SMEM_WORDS (2*144*KP + 144*VP + 2*144*KP)

__global__ void __launch_bounds__(288, 2)
attn_kernel(const float* __restrict__ mask,
            const float* __restrict__ logit_scale,
            float* __restrict__ attout)
{
    const int bh = blockIdx.x;
    const int b = bh >> 4;
    const int h = bh & 15;
    const int win = b & (NWIN - 1);

    const int tid = threadIdx.x;
    const int w = tid >> 5, lane = tid & 31;
    const int g = lane >> 2, tg = lane & 3;

    extern __shared__ uint32_t sm_u[];
    uint32_t* ksh = sm_u;                    // [144][KP]
    uint32_t* ksl = ksh + 144 * KP;          // [144][KP]
    uint32_t* vsm = ksl + 144 * KP;          // [144][VP]  (row-major, tf32)
    uint32_t* qsh = vsm + 144 * VP;          // [144][KP]
    uint32_t* qsl = qsh + 144 * KP;          // [144][KP]
    uint32_t* pstrip = qsh;                  // alias: [9][16][SP] after barrier

    const float scale = expf(fminf(logit_scale[h], LOG100));

    const float* qbase = g_qkv + (size_t)(b * SEQ) * 1536 + h * 32;
    const float* kbase = qbase + 512;
    const float* vbase = qbase + 1024;

    // ---- load K (normalized, hi/lo split) and V (tf32), 2 threads/row ----
    {
        int r = tid >> 1, half = tid & 1;
        const float4* kr = (const float4*)(kbase + (size_t)r * 1536 + half * 16);
        float kv[16];
        float sq = 0.f;
#pragma unroll
        for (int i4 = 0; i4 < 4; i4++) {
            float4 f = kr[i4];
            kv[i4*4+0] = f.x; kv[i4*4+1] = f.y; kv[i4*4+2] = f.z; kv[i4*4+3] = f.w;
            sq += f.x*f.x + f.y*f.y + f.z*f.z + f.w*f.w;
        }
        sq += __shfl_xor_sync(0xffffffffu, sq, 1);
        float inv = 1.f / fmaxf(sqrtf(sq), 1e-12f);
#pragma unroll
        for (int i = 0; i < 16; i++) {
            int d = half * 16 + i;
            float f = kv[i] * inv;
            uint32_t hi = f2tf32(f);
            float lo = f - __uint_as_float(hi);
            ksh[r * KP + d] = hi;
            ksl[r * KP + d] = f2tf32(lo);
        }
        const float4* vr = (const float4*)(vbase + (size_t)r * 1536 + half * 16);
#pragma unroll
        for (int i4 = 0; i4 < 4; i4++) {
            float4 f = vr[i4];
            int d = half * 16 + i4 * 4;
            vsm[r * VP + d + 0] = f2tf32(f.x);
            vsm[r * VP + d + 1] = f2tf32(f.y);
            vsm[r * VP + d + 2] = f2tf32(f.z);
            vsm[r * VP + d + 3] = f2tf32(f.w);
        }
    }

    // ---- load Q rows for this warp (normalized, scaled, hi/lo split) ----
#pragma unroll
    for (int rr = 0; rr < 16; rr++) {
        int row = w * 16 + rr;
        float qv = qbase[(size_t)row * 1536 + lane];
        float sq = qv * qv;
#pragma unroll
        for (int off = 16; off > 0; off >>= 1)
            sq += __shfl_xor_sync(0xffffffffu, sq, off);
        float inv = scale / fmaxf(sqrtf(sq), 1e-12f);
        float f = qv * inv;
        uint32_t hi = f2tf32(f);
        float lo = f - __uint_as_float(hi);
        qsh[row * KP + lane] = hi;
        qsl[row * KP + lane] = f2tf32(lo);
    }
    __syncthreads();

    // ---- Q A-fragments (hi & lo) for all 4 k-tiles ----
    uint32_t ah[4][4], al[4][4];
#pragma unroll
    for (int kt = 0; kt < 4; kt++) {
        const uint32_t* p = qsh + (w * 16 + g) * KP + kt * 8 + tg;
        ah[kt][0] = p[0]; ah[kt][2] = p[4];
        const uint32_t* p2 = p + 8 * KP;
        ah[kt][1] = p2[0]; ah[kt][3] = p2[4];
        const uint32_t* q = qsl + (w * 16 + g) * KP + kt * 8 + tg;
        al[kt][0] = q[0]; al[kt][2] = q[4];
        const uint32_t* q2 = q + 8 * KP;
        al[kt][1] = q2[0]; al[kt][3] = q2[4];
    }
    __syncthreads();   // Q region dead; pstrip aliasing now safe

    // ---- online softmax state ----
    const float NEG_INF = __int_as_float(0xff800000);
    float m0r = NEG_INF, m1r = NEG_INF;   // running row max (rows g, g+8)
    float s0r = 0.f, s1r = 0.f;           // per-lane partial running sums
    float oc[4][4];
#pragma unroll
    for (int nt = 0; nt < 4; nt++)
#pragma unroll
        for (int r = 0; r < 4; r++) oc[nt][r] = 0.f;

    uint32_t* pw = pstrip + w * 16 * SP;
    const float* mrow = mask + (size_t)win * SEQ * SEQ
                      + (size_t)(w * 16 + g) * SEQ + 2 * tg;

    // ---- 6 strips of 24 keys ----
#pragma unroll 1
    for (int s = 0; s < 6; s++) {
        float sacc[3][4];
#pragma unroll
        for (int j = 0; j < 3; j++)
#pragma unroll
            for (int r = 0; r < 4; r++) sacc[j][r] = 0.f;

#pragma unroll
        for (int j = 0; j < 3; j++) {
            int nt = 3 * s + j;
#pragma unroll
            for (int kt = 0; kt < 4; kt++) {
                const uint32_t* p = ksh + (nt * 8 + g) * KP + kt * 8 + tg;
                uint32_t bh0 = p[0], bh1 = p[4];
                const uint32_t* q = ksl + (nt * 8 + g) * KP + kt * 8 + tg;
                uint32_t bl0 = q[0], bl1 = q[4];
                mma8(sacc[j], ah[kt], bh0, bh1);
                mma8(sacc[j], al[kt], bh0, bh1);
                mma8(sacc[j], ah[kt], bl0, bl1);
            }
        }

        // add mask; strip max per row
        float mx0 = NEG_INF, mx1 = NEG_INF;
#pragma unroll
        for (int j = 0; j < 3; j++) {
            int nt = 3 * s + j;
            float2 mk0 = *(const float2*)(mrow + nt * 8);
            float2 mk1 = *(const float2*)(mrow + 8 * SEQ + nt * 8);
            sacc[j][0] += mk0.x; sacc[j][1] += mk0.y;
            sacc[j][2] += mk1.x; sacc[j][3] += mk1.y;
            mx0 = fmaxf(mx0, fmaxf(sacc[j][0], sacc[j][1]));
            mx1 = fmaxf(mx1, fmaxf(sacc[j][2], sacc[j][3]));
        }
        mx0 = fmaxf(mx0, __shfl_xor_sync(0xffffffffu, mx0, 1));
        mx0 = fmaxf(mx0, __shfl_xor_sync(0xffffffffu, mx0, 2));
        mx1 = fmaxf(mx1, __shfl_xor_sync(0xffffffffu, mx1, 1));
        mx1 = fmaxf(mx1, __shfl_xor_sync(0xffffffffu, mx1, 2));

        float mn0 = fmaxf(m0r, mx0), mn1 = fmaxf(m1r, mx1);
        float f0 = __expf(m0r - mn0), f1 = __expf(m1r - mn1);
        m0r = mn0; m1r = mn1;
        s0r *= f0; s1r *= f1;
#pragma unroll
        for (int nt = 0; nt < 4; nt++) {
            oc[nt][0] *= f0; oc[nt][1] *= f0;
            oc[nt][2] *= f1; oc[nt][3] *= f1;
        }

        // exp, accumulate partial sums, write P strip (unnormalized, tf32)
#pragma unroll
        for (int j = 0; j < 3; j++) {
            float p0 = __expf(sacc[j][0] - mn0);
            float p1 = __expf(sacc[j][1] - mn0);
            float p2 = __expf(sacc[j][2] - mn1);
            float p3 = __expf(sacc[j][3] - mn1);
            s0r += p0 + p1;
            s1r += p2 + p3;
            uint32_t* d0 = pw + g * SP + j * 8 + 2 * tg;
            d0[0] = f2tf32(p0); d0[1] = f2tf32(p1);
            uint32_t* d1 = pw + (g + 8) * SP + j * 8 + 2 * tg;
            d1[0] = f2tf32(p2); d1[1] = f2tf32(p3);
        }
        __syncwarp();

        // PV: O += P_strip @ V[24 keys]
#pragma unroll
        for (int kt2 = 0; kt2 < 3; kt2++) {
            uint32_t a[4];
            const uint32_t* p = pw + g * SP + kt2 * 8 + tg;
            a[0] = p[0]; a[2] = p[4];
            const uint32_t* p2 = pw + (g + 8) * SP + kt2 * 8 + tg;
            a[1] = p2[0]; a[3] = p2[4];
            int key0 = s * 24 + kt2 * 8;
#pragma unroll
            for (int nt = 0; nt < 4; nt++) {
                uint32_t b0 = vsm[(key0 + tg) * VP + nt * 8 + g];
                uint32_t b1 = vsm[(key0 + tg + 4) * VP + nt * 8 + g];
                mma8(oc[nt], a, b0, b1);
            }
        }
        __syncwarp();
    }

    // ---- finalize: reduce sums over tg lanes, divide, store ----
    s0r += __shfl_xor_sync(0xffffffffu, s0r, 1);
    s0r += __shfl_xor_sync(0xffffffffu, s0r, 2);
    s1r += __shfl_xor_sync(0xffffffffu, s1r, 1);
    s1r += __shfl_xor_sync(0xffffffffu, s1r, 2);
    float inv0 = 1.f / s0r, inv1 = 1.f / s1r;

    const int row0 = b * SEQ + w * 16 + g;
#pragma unroll
    for (int nt = 0; nt < 4; nt++) {
        int col = h * 32 + nt * 8 + 2 * tg;
        *(float2*)(attout + (size_t)row0 * 512 + col) =
            make_float2(oc[nt][0] * inv0, oc[nt][1] * inv0);
        *(float2*)(attout + (size_t)(row0 + 8) * 512 + col) =
            make_float2(oc[nt][2] * inv1, oc[nt][3] * inv1);
    }
}

// ============================================================
// launch
// ============================================================
extern "C" void kernel_launch(void* const* d_in, const int* in_sizes, int n_in,
                              void* d_out, int out_size)
{
    (void)in_sizes; (void)n_in; (void)out_size;
    const float* x    = (const float*)d_in[0];
    const float* mask = (const float*)d_in[1];
    const float* Wq   = (const float*)d_in[2];
    const float* bq   = (const float*)d_in[3];
    const float* Wk   = (const float*)d_in[4];
    const float* bk   = (const float*)d_in[5];
    const float* Wv   = (const float*)d_in[6];
    const float* bv   = (const float*)d_in[7];
    const float* Wp   = (const float*)d_in[8];
    const float* bp   = (const float*)d_in[9];
    const float* ls   = (const float*)d_in[10];
    float* out = (float*)d_out;

    void* qkv_p = nullptr;
    void* att_p = nullptr;
    cudaGetSymbolAddress(&qkv_p, g_qkv);
    cudaGetSymbolAddress(&att_p, g_att);
    float* qkv = (float*)qkv_p;
    float* att = (float*)att_p;

    const int gemm_smem = 2 * 2 * 128 * APAD * 4;          // 73728 B
    const int att_smem  = ATT_SMEM_WORDS * 4;              // 105984 B
    cudaFuncSetAttribute(gemm_tf32_kernel,
                         cudaFuncAttributeMaxDynamicSharedMemorySize, gemm_smem);
    cudaFuncSetAttribute(attn_kernel,
                         cudaFuncAttributeMaxDynamicSharedMemorySize, att_smem);

    // QKV projections (z folded into grid.x: 12 = 4 N-tiles * 3 matrices)
    dim3 gq(12, MROWS / 128, 1);
    gemm_tf32_kernel<<<gq, 256, gemm_smem>>>(x, Wq, Wk, Wv, bq, bk, bv,
                                             qkv, 1536, CH);

    // attention (flash-style, tensor-core)
    attn_kernel<<<BW * NH, 288, att_smem>>>(mask, ls, att);

    // output projection
    dim3 gp(4, MROWS / 128, 1);
    gemm_tf32_kernel<<<gp, 256, gemm_smem>>>(att, Wp, Wp, Wp, bp, bp, bp,
                                             out, 512, CH);
}

// round 5
// speedup vs baseline: 1.6922x; 1.0637x over previous
#include <cuda_runtime.h>
#include <cstdint>

// ---------------- problem constants ----------------
#define BW    1024
#define SEQ   144
#define CH    512
#define NH    16
#define DH    32
#define NWIN  64
#define MROWS (BW*SEQ)          // 147456
#define LOG100 4.6051701859880913680f

// ---------------- scratch (device globals; no cudaMalloc allowed) ----------
__device__ float g_qkv[(size_t)MROWS * 1536];   // q|k|v concatenated per row (fp32)
__device__ float g_att[(size_t)MROWS * 512];    // attention out, tf32-rounded
__device__ float g_xt[(size_t)MROWS * 512];     // x rounded to tf32
__device__ float g_wt[4 * 512 * 512];           // Wq|Wk|Wv|Wp rounded to tf32

// ---------------- helpers ----------------
__device__ __forceinline__ uint32_t f2tf32(float f) {
    uint32_t u;
    asm("cvt.rna.tf32.f32 %0, %1;" : "=r"(u) : "f"(f));
    return u;
}
__device__ __forceinline__ float rtf(float f) { return __uint_as_float(f2tf32(f)); }

__device__ __forceinline__ uint32_t smem_u32(const void* p) {
    uint32_t a;
    asm("{ .reg .u64 t; cvta.to.shared.u64 t, %1; cvt.u32.u64 %0, t; }" : "=r"(a) : "l"(p));
    return a;
}

__device__ __forceinline__ void mma8(float* c, const uint32_t* a, uint32_t b0, uint32_t b1) {
    asm volatile(
        "mma.sync.aligned.m16n8k8.row.col.f32.tf32.tf32.f32 "
        "{%0,%1,%2,%3}, {%4,%5,%6,%7}, {%8,%9}, {%0,%1,%2,%3};\n"
        : "+f"(c[0]), "+f"(c[1]), "+f"(c[2]), "+f"(c[3])
        : "r"(a[0]), "r"(a[1]), "r"(a[2]), "r"(a[3]), "r"(b0), "r"(b1));
}

__device__ __forceinline__ void cp16(uint32_t dst, const void* src) {
    asm volatile("cp.async.cg.shared.global [%0], [%1], 16;" :: "r"(dst), "l"(src));
}

// ============================================================
// GEMM: C[m, z*512 + n] = A[m,:] . B_z[n,:] + bias_z[n]
// Inputs pre-rounded to tf32 in global. cp.async 2-stage pipeline.
// 128 threads, 4 warps (2x2), warp tile 64x64, CTA tile 128x128.
// ============================================================
#define APAD 36
#define AS_OFF(s) ((s) * 128 * APAD)
#define BS_OFF(s) (2 * 128 * APAD + (s) * 128 * APAD)
#define GEMM_SMEM (4 * 128 * APAD * 4)   // 73728 B

__global__ void __launch_bounds__(128, 2)
gemm_tf32_kernel(const float* __restrict__ A,
                 const float* __restrict__ B0, const float* __restrict__ B1,
                 const float* __restrict__ B2,
                 const float* __restrict__ bias0, const float* __restrict__ bias1,
                 const float* __restrict__ bias2,
                 float* __restrict__ Cout, int ldc)
{
    const int z  = blockIdx.x >> 2;
    const int nb = blockIdx.x & 3;
    const float* B    = (z == 0) ? B0 : (z == 1 ? B1 : B2);
    const float* bias = (z == 0) ? bias0 : (z == 1 ? bias1 : bias2);

    const int m0 = blockIdx.y * 128;
    const int n0 = nb * 128;

    extern __shared__ uint32_t smem_u[];
    const uint32_t sb = smem_u32(smem_u);

    const int tid  = threadIdx.x;
    const int warp = tid >> 5, lane = tid & 31;
    const int wm = warp & 1;          // M half (64 rows)
    const int wn = warp >> 1;         // N half (64 cols)
    const int g  = lane >> 2, tg = lane & 3;

    const int r8 = tid >> 3;          // 0..15 copy base row
    const int c4 = (tid & 7) * 4;     // 0,4,..28 copy col

    const float* Abase = A + (size_t)(m0 + r8) * 512 + c4;
    const float* Bbase = B + (size_t)(n0 + r8) * 512 + c4;

    float acc[4][8][4];
#pragma unroll
    for (int i = 0; i < 4; i++)
#pragma unroll
        for (int j = 0; j < 8; j++)
#pragma unroll
            for (int r = 0; r < 4; r++) acc[i][j][r] = 0.f;

    // prologue: stages 0,1 (k-chunks 0,1)
#pragma unroll
    for (int s = 0; s < 2; s++) {
        uint32_t ad = sb + (AS_OFF(s) + r8 * APAD + c4) * 4;
        uint32_t bd = sb + (BS_OFF(s) + r8 * APAD + c4) * 4;
#pragma unroll
        for (int i = 0; i < 8; i++) {
            cp16(ad + i * 16 * APAD * 4, Abase + s * 32 + (size_t)i * 16 * 512);
            cp16(bd + i * 16 * APAD * 4, Bbase + s * 32 + (size_t)i * 16 * 512);
        }
        asm volatile("cp.async.commit_group;" ::: "memory");
    }

#pragma unroll 1
    for (int kt = 0; kt < 16; kt++) {
        const int s = kt & 1;
        if (kt < 15)
            asm volatile("cp.async.wait_group 1;" ::: "memory");
        else
            asm volatile("cp.async.wait_group 0;" ::: "memory");
        __syncthreads();

        const uint32_t* Ab = smem_u + AS_OFF(s);
        const uint32_t* Bb = smem_u + BS_OFF(s);
#pragma unroll
        for (int ks = 0; ks < 4; ks++) {
            uint32_t af[4][4];
#pragma unroll
            for (int mi = 0; mi < 4; mi++) {
                const uint32_t* p = Ab + (wm * 64 + mi * 16 + g) * APAD + ks * 8 + tg;
                af[mi][0] = p[0];
                af[mi][2] = p[4];
                af[mi][1] = p[8 * APAD];
                af[mi][3] = p[8 * APAD + 4];
            }
#pragma unroll
            for (int ni = 0; ni < 8; ni++) {
                const uint32_t* p = Bb + (wn * 64 + ni * 8 + g) * APAD + ks * 8 + tg;
                uint32_t b0 = p[0], b1 = p[4];
#pragma unroll
                for (int mi = 0; mi < 4; mi++)
                    mma8(acc[mi][ni], af[mi], b0, b1);
            }
        }
        __syncthreads();

        if (kt + 2 < 16) {
            uint32_t ad = sb + (AS_OFF(s) + r8 * APAD + c4) * 4;
            uint32_t bd = sb + (BS_OFF(s) + r8 * APAD + c4) * 4;
#pragma unroll
            for (int i = 0; i < 8; i++) {
                cp16(ad + i * 16 * APAD * 4, Abase + (kt + 2) * 32 + (size_t)i * 16 * 512);
                cp16(bd + i * 16 * APAD * 4, Bbase + (kt + 2) * 32 + (size_t)i * 16 * 512);
            }
            asm volatile("cp.async.commit_group;" ::: "memory");
        }
    }

    // epilogue
#pragma unroll
    for (int mi = 0; mi < 4; mi++) {
        int row = m0 + wm * 64 + mi * 16 + g;
#pragma unroll
        for (int ni = 0; ni < 8; ni++) {
            int ncol = n0 + wn * 64 + ni * 8 + 2 * tg;
            int gcol = z * 512 + ncol;
            float b0 = bias[ncol], b1 = bias[ncol + 1];
            float2 v0 = make_float2(acc[mi][ni][0] + b0, acc[mi][ni][1] + b1);
            float2 v1 = make_float2(acc[mi][ni][2] + b0, acc[mi][ni][3] + b1);
            *(float2*)(Cout + (size_t)row * ldc + gcol) = v0;
            *(float2*)(Cout + (size_t)(row + 8) * ldc + gcol) = v1;
        }
    }
}

// ============================================================
// conversion kernels (fp32 -> tf32-rounded fp32 in global)
// ============================================================
__global__ void convert_x_kernel(const float* __restrict__ x, float* __restrict__ o)
{
    size_t i = (size_t)blockIdx.x * 256 + threadIdx.x;
    float4 v = ((const float4*)x)[i];
    ((uint4*)o)[i] = make_uint4(f2tf32(v.x), f2tf32(v.y), f2tf32(v.z), f2tf32(v.w));
}

__global__ void convert_w_kernel(const float* __restrict__ w0, const float* __restrict__ w1,
                                 const float* __restrict__ w2, const float* __restrict__ w3,
                                 float* __restrict__ o)
{
    size_t i = (size_t)blockIdx.x * 256 + threadIdx.x;
    const float* srcs[4] = {w0, w1, w2, w3};
#pragma unroll
    for (int m = 0; m < 4; m++) {
        float4 v = ((const float4*)srcs[m])[i];
        ((uint4*)(o + (size_t)m * 262144))[i] =
            make_uint4(f2tf32(v.x), f2tf32(v.y), f2tf32(v.z), f2tf32(v.w));
    }
}

// ============================================================
// Attention: flash-style online softmax on tensor cores (mma.sync).
// One CTA per (b,h), 9 warps, warp owns 16 q-rows. 24-key strips.
// Output stores tf32-rounded (feeds out-proj exactly).
// ============================================================
#define KP 36
#define VP 40
#define SP 36
#define ATT_SMEM_WORDS (2*144*KP + 144*VP + 2*144*KP)

__global__ void __launch_bounds__(288, 2)
attn_kernel(const float* __restrict__ mask,
            const float* __restrict__ logit_scale,
            float* __restrict__ attout)
{
    const int bh = blockIdx.x;
    const int b = bh >> 4;
    const int h = bh & 15;
    const int win = b & (NWIN - 1);

    const int tid = threadIdx.x;
    const int w = tid >> 5, lane = tid & 31;
    const int g = lane >> 2, tg = lane & 3;

    extern __shared__ uint32_t sm_u[];
    uint32_t* ksh = sm_u;                    // [144][KP]
    uint32_t* ksl = ksh + 144 * KP;          // [144][KP]
    uint32_t* vsm = ksl + 144 * KP;          // [144][VP]
    uint32_t* qsh = vsm + 144 * VP;          // [144][KP]
    uint32_t* qsl = qsh + 144 * KP;          // [144][KP]
    uint32_t* pstrip = qsh;                  // alias after barrier

    const float scale = expf(fminf(logit_scale[h], LOG100));

    const float* qbase = g_qkv + (size_t)(b * SEQ) * 1536 + h * 32;
    const float* kbase = qbase + 512;
    const float* vbase = qbase + 1024;

    {
        int r = tid >> 1, half = tid & 1;
        const float4* kr = (const float4*)(kbase + (size_t)r * 1536 + half * 16);
        float kv[16];
        float sq = 0.f;
#pragma unroll
        for (int i4 = 0; i4 < 4; i4++) {
            float4 f = kr[i4];
            kv[i4*4+0] = f.x; kv[i4*4+1] = f.y; kv[i4*4+2] = f.z; kv[i4*4+3] = f.w;
            sq += f.x*f.x + f.y*f.y + f.z*f.z + f.w*f.w;
        }
        sq += __shfl_xor_sync(0xffffffffu, sq, 1);
        float inv = 1.f / fmaxf(sqrtf(sq), 1e-12f);
#pragma unroll
        for (int i = 0; i < 16; i++) {
            int d = half * 16 + i;
            float f = kv[i] * inv;
            uint32_t hi = f2tf32(f);
            float lo = f - __uint_as_float(hi);
            ksh[r * KP + d] = hi;
            ksl[r * KP + d] = f2tf32(lo);
        }
        const float4* vr = (const float4*)(vbase + (size_t)r * 1536 + half * 16);
#pragma unroll
        for (int i4 = 0; i4 < 4; i4++) {
            float4 f = vr[i4];
            int d = half * 16 + i4 * 4;
            vsm[r * VP + d + 0] = f2tf32(f.x);
            vsm[r * VP + d + 1] = f2tf32(f.y);
            vsm[r * VP + d + 2] = f2tf32(f.z);
            vsm[r * VP + d + 3] = f2tf32(f.w);
        }
    }

#pragma unroll
    for (int rr = 0; rr < 16; rr++) {
        int row = w * 16 + rr;
        float qv = qbase[(size_t)row * 1536 + lane];
        float sq = qv * qv;
#pragma unroll
        for (int off = 16; off > 0; off >>= 1)
            sq += __shfl_xor_sync(0xffffffffu, sq, off);
        float inv = scale / fmaxf(sqrtf(sq), 1e-12f);
        float f = qv * inv;
        uint32_t hi = f2tf32(f);
        float lo = f - __uint_as_float(hi);
        qsh[row * KP + lane] = hi;
        qsl[row * KP + lane] = f2tf32(lo);
    }
    __syncthreads();

    uint32_t ah[4][4], al[4][4];
#pragma unroll
    for (int kt = 0; kt < 4; kt++) {
        const uint32_t* p = qsh + (w * 16 + g) * KP + kt * 8 + tg;
        ah[kt][0] = p[0]; ah[kt][2] = p[4];
        const uint32_t* p2 = p + 8 * KP;
        ah[kt][1] = p2[0]; ah[kt][3] = p2[4];
        const uint32_t* q = qsl + (w * 16 + g) * KP + kt * 8 + tg;
        al[kt][0] = q[0]; al[kt][2] = q[4];
        const uint32_t* q2 = q + 8 * KP;
        al[kt][1] = q2[0]; al[kt][3] = q2[4];
    }
    __syncthreads();   // Q region dead; pstrip aliasing safe

    const float NEG_INF = __int_as_float(0xff800000);
    float m0r = NEG_INF, m1r = NEG_INF;
    float s0r = 0.f, s1r = 0.f;
    float oc[4][4];
#pragma unroll
    for (int nt = 0; nt < 4; nt++)
#pragma unroll
        for (int r = 0; r < 4; r++) oc[nt][r] = 0.f;

    uint32_t* pw = pstrip + w * 16 * SP;
    const float* mrow = mask + (size_t)win * SEQ * SEQ
                      + (size_t)(w * 16 + g) * SEQ + 2 * tg;

#pragma unroll 1
    for (int s = 0; s < 6; s++) {
        float sacc[3][4];
#pragma unroll
        for (int j = 0; j < 3; j++)
#pragma unroll
            for (int r = 0; r < 4; r++) sacc[j][r] = 0.f;

#pragma unroll
        for (int j = 0; j < 3; j++) {
            int nt = 3 * s + j;
#pragma unroll
            for (int kt = 0; kt < 4; kt++) {
                const uint32_t* p = ksh + (nt * 8 + g) * KP + kt * 8 + tg;
                uint32_t bh0 = p[0], bh1 = p[4];
                const uint32_t* q = ksl + (nt * 8 + g) * KP + kt * 8 + tg;
                uint32_t bl0 = q[0], bl1 = q[4];
                mma8(sacc[j], ah[kt], bh0, bh1);
                mma8(sacc[j], al[kt], bh0, bh1);
                mma8(sacc[j], ah[kt], bl0, bl1);
            }
        }

        float mx0 = NEG_INF, mx1 = NEG_INF;
#pragma unroll
        for (int j = 0; j < 3; j++) {
            int nt = 3 * s + j;
            float2 mk0 = *(const float2*)(mrow + nt * 8);
            float2 mk1 = *(const float2*)(mrow + 8 * SEQ + nt * 8);
            sacc[j][0] += mk0.x; sacc[j][1] += mk0.y;
            sacc[j][2] += mk1.x; sacc[j][3] += mk1.y;
            mx0 = fmaxf(mx0, fmaxf(sacc[j][0], sacc[j][1]));
            mx1 = fmaxf(mx1, fmaxf(sacc[j][2], sacc[j][3]));
        }
        mx0 = fmaxf(mx0, __shfl_xor_sync(0xffffffffu, mx0, 1));
        mx0 = fmaxf(mx0, __shfl_xor_sync(0xffffffffu, mx0, 2));
        mx1 = fmaxf(mx1, __shfl_xor_sync(0xffffffffu, mx1, 1));
        mx1 = fmaxf(mx1, __shfl_xor_sync(0xffffffffu, mx1, 2));

        float mn0 = fmaxf(m0r, mx0), mn1 = fmaxf(m1r, mx1);
        float f0 = __expf(m0r - mn0), f1 = __expf(m1r - mn1);
        m0r = mn0; m1r = mn1;
        s0r *= f0; s1r *= f1;
#pragma unroll
        for (int nt = 0; nt < 4; nt++) {
            oc[nt][0] *= f0; oc[nt][1] *= f0;
            oc[nt][2] *= f1; oc[nt][3] *= f1;
        }

#pragma unroll
        for (int j = 0; j < 3; j++) {
            float p0 = __expf(sacc[j][0] - mn0);
            float p1 = __expf(sacc[j][1] - mn0);
            float p2 = __expf(sacc[j][2] - mn1);
            float p3 = __expf(sacc[j][3] - mn1);
            s0r += p0 + p1;
            s1r += p2 + p3;
            uint32_t* d0 = pw + g * SP + j * 8 + 2 * tg;
            d0[0] = f2tf32(p0); d0[1] = f2tf32(p1);
            uint32_t* d1 = pw + (g + 8) * SP + j * 8 + 2 * tg;
            d1[0] = f2tf32(p2); d1[1] = f2tf32(p3);
        }
        __syncwarp();

#pragma unroll
        for (int kt2 = 0; kt2 < 3; kt2++) {
            uint32_t a[4];
            const uint32_t* p = pw + g * SP + kt2 * 8 + tg;
            a[0] = p[0]; a[2] = p[4];
            const uint32_t* p2 = pw + (g + 8) * SP + kt2 * 8 + tg;
            a[1] = p2[0]; a[3] = p2[4];
            int key0 = s * 24 + kt2 * 8;
#pragma unroll
            for (int nt = 0; nt < 4; nt++) {
                uint32_t b0 = vsm[(key0 + tg) * VP + nt * 8 + g];
                uint32_t b1 = vsm[(key0 + tg + 4) * VP + nt * 8 + g];
                mma8(oc[nt], a, b0, b1);
            }
        }
        __syncwarp();
    }

    s0r += __shfl_xor_sync(0xffffffffu, s0r, 1);
    s0r += __shfl_xor_sync(0xffffffffu, s0r, 2);
    s1r += __shfl_xor_sync(0xffffffffu, s1r, 1);
    s1r += __shfl_xor_sync(0xffffffffu, s1r, 2);
    float inv0 = 1.f / s0r, inv1 = 1.f / s1r;

    const int row0 = b * SEQ + w * 16 + g;
#pragma unroll
    for (int nt = 0; nt < 4; nt++) {
        int col = h * 32 + nt * 8 + 2 * tg;
        *(float2*)(attout + (size_t)row0 * 512 + col) =
            make_float2(rtf(oc[nt][0] * inv0), rtf(oc[nt][1] * inv0));
        *(float2*)(attout + (size_t)(row0 + 8) * 512 + col) =
            make_float2(rtf(oc[nt][2] * inv1), rtf(oc[nt][3] * inv1));
    }
}

// ============================================================
// launch
// ============================================================
extern "C" void kernel_launch(void* const* d_in, const int* in_sizes, int n_in,
                              void* d_out, int out_size)
{
    (void)in_sizes; (void)n_in; (void)out_size;
    const float* x    = (const float*)d_in[0];
    const float* mask = (const float*)d_in[1];
    const float* Wq   = (const float*)d_in[2];
    const float* bq   = (const float*)d_in[3];
    const float* Wk   = (const float*)d_in[4];
    const float* bk   = (const float*)d_in[5];
    const float* Wv   = (const float*)d_in[6];
    const float* bv   = (const float*)d_in[7];
    const float* Wp   = (const float*)d_in[8];
    const float* bp   = (const float*)d_in[9];
    const float* ls   = (const float*)d_in[10];
    float* out = (float*)d_out;

    void *qkv_p = nullptr, *att_p = nullptr, *xt_p = nullptr, *wt_p = nullptr;
    cudaGetSymbolAddress(&qkv_p, g_qkv);
    cudaGetSymbolAddress(&att_p, g_att);
    cudaGetSymbolAddress(&xt_p, g_xt);
    cudaGetSymbolAddress(&wt_p, g_wt);
    float* qkv = (float*)qkv_p;
    float* att = (float*)att_p;
    float* xt  = (float*)xt_p;
    float* wt  = (float*)wt_p;

    const int att_smem = ATT_SMEM_WORDS * 4;               // 105984 B
    cudaFuncSetAttribute(gemm_tf32_kernel,
                         cudaFuncAttributeMaxDynamicSharedMemorySize, GEMM_SMEM);
    cudaFuncSetAttribute(attn_kernel,
                         cudaFuncAttributeMaxDynamicSharedMemorySize, att_smem);

    // 0) round inputs to tf32 (in global)
    convert_x_kernel<<<MROWS * 512 / 4 / 256, 256>>>(x, xt);
    convert_w_kernel<<<256, 256>>>(Wq, Wk, Wv, Wp, wt);

    // 1) QKV projections: grid.x = 4 n-tiles * 3 z
    gemm_tf32_kernel<<<dim3(12, MROWS / 128), 128, GEMM_SMEM>>>(
        xt, wt, wt + 262144, wt + 2 * 262144, bq, bk, bv, qkv, 1536);

    // 2) attention (flash, mma.sync)
    attn_kernel<<<BW * NH, 288, att_smem>>>(mask, ls, att);

    // 3) output projection
    gemm_tf32_kernel<<<dim3(4, MROWS / 128), 128, GEMM_SMEM>>>(
        att, wt + 3 * 262144, wt + 3 * 262144, wt + 3 * 262144, bp, bp, bp, out, 512);
}

// round 6
// speedup vs baseline: 1.9886x; 1.1751x over previous
#include <cuda_runtime.h>
#include <cstdint>

// ---------------- problem constants ----------------
#define BW    1024
#define SEQ   144
#define CH    512
#define NH    16
#define DH    32
#define NWIN  64
#define MROWS (BW*SEQ)          // 147456
#define LOG100 4.6051701859880913680f

// ---------------- scratch (device globals; no cudaMalloc allowed) ----------
__device__ float g_qkv[(size_t)MROWS * 1536];   // q|k|v concatenated per row (fp32)
__device__ float g_att[(size_t)MROWS * 512];    // attention out, tf32-rounded
__device__ float g_xt[(size_t)MROWS * 512];     // x rounded to tf32
__device__ float g_wt[4 * 512 * 512];           // Wq|Wk|Wv|Wp rounded to tf32

// ---------------- helpers ----------------
__device__ __forceinline__ uint32_t f2tf32(float f) {
    uint32_t u;
    asm("cvt.rna.tf32.f32 %0, %1;" : "=r"(u) : "f"(f));
    return u;
}
__device__ __forceinline__ float rtf(float f) { return __uint_as_float(f2tf32(f)); }

__device__ __forceinline__ uint32_t smem_u32(const void* p) {
    uint32_t a;
    asm("{ .reg .u64 t; cvta.to.shared.u64 t, %1; cvt.u32.u64 %0, t; }" : "=r"(a) : "l"(p));
    return a;
}

__device__ __forceinline__ void mma8(float* c, const uint32_t* a, uint32_t b0, uint32_t b1) {
    asm volatile(
        "mma.sync.aligned.m16n8k8.row.col.f32.tf32.tf32.f32 "
        "{%0,%1,%2,%3}, {%4,%5,%6,%7}, {%8,%9}, {%0,%1,%2,%3};\n"
        : "+f"(c[0]), "+f"(c[1]), "+f"(c[2]), "+f"(c[3])
        : "r"(a[0]), "r"(a[1]), "r"(a[2]), "r"(a[3]), "r"(b0), "r"(b1));
}

__device__ __forceinline__ void cp16(uint32_t dst, const void* src) {
    asm volatile("cp.async.cg.shared.global [%0], [%1], 16;" :: "r"(dst), "l"(src));
}

// ============================================================
// GEMM: C[m, z*512 + n] = A[m,:] . B_z[n,:] + bias_z[n]
// Inputs pre-rounded to tf32 in global. cp.async 2-stage pipeline.
// 128 threads, 4 warps (2x2), warp tile 64x64, CTA tile 128x128.
// 3 CTAs / SM (regs 128, smem 73.7KB -> 221KB).
// ============================================================
#define APAD 36
#define AS_OFF(s) ((s) * 128 * APAD)
#define BS_OFF(s) (2 * 128 * APAD + (s) * 128 * APAD)
#define GEMM_SMEM (4 * 128 * APAD * 4)   // 73728 B

__global__ void __launch_bounds__(128, 3)
gemm_tf32_kernel(const float* __restrict__ A,
                 const float* __restrict__ B0, const float* __restrict__ B1,
                 const float* __restrict__ B2,
                 const float* __restrict__ bias0, const float* __restrict__ bias1,
                 const float* __restrict__ bias2,
                 float* __restrict__ Cout, int ldc)
{
    const int z  = blockIdx.x >> 2;
    const int nb = blockIdx.x & 3;
    const float* B    = (z == 0) ? B0 : (z == 1 ? B1 : B2);
    const float* bias = (z == 0) ? bias0 : (z == 1 ? bias1 : bias2);

    const int m0 = blockIdx.y * 128;
    const int n0 = nb * 128;

    extern __shared__ uint32_t smem_u[];
    const uint32_t sb = smem_u32(smem_u);

    const int tid  = threadIdx.x;
    const int warp = tid >> 5, lane = tid & 31;
    const int wm = warp & 1;
    const int wn = warp >> 1;
    const int g  = lane >> 2, tg = lane & 3;

    const int r8 = tid >> 3;
    const int c4 = (tid & 7) * 4;

    const float* Abase = A + (size_t)(m0 + r8) * 512 + c4;
    const float* Bbase = B + (size_t)(n0 + r8) * 512 + c4;

    float acc[4][8][4];
#pragma unroll
    for (int i = 0; i < 4; i++)
#pragma unroll
        for (int j = 0; j < 8; j++)
#pragma unroll
            for (int r = 0; r < 4; r++) acc[i][j][r] = 0.f;

#pragma unroll
    for (int s = 0; s < 2; s++) {
        uint32_t ad = sb + (AS_OFF(s) + r8 * APAD + c4) * 4;
        uint32_t bd = sb + (BS_OFF(s) + r8 * APAD + c4) * 4;
#pragma unroll
        for (int i = 0; i < 8; i++) {
            cp16(ad + i * 16 * APAD * 4, Abase + s * 32 + (size_t)i * 16 * 512);
            cp16(bd + i * 16 * APAD * 4, Bbase + s * 32 + (size_t)i * 16 * 512);
        }
        asm volatile("cp.async.commit_group;" ::: "memory");
    }

#pragma unroll 1
    for (int kt = 0; kt < 16; kt++) {
        const int s = kt & 1;
        if (kt < 15)
            asm volatile("cp.async.wait_group 1;" ::: "memory");
        else
            asm volatile("cp.async.wait_group 0;" ::: "memory");
        __syncthreads();

        const uint32_t* Ab = smem_u + AS_OFF(s);
        const uint32_t* Bb = smem_u + BS_OFF(s);
#pragma unroll
        for (int ks = 0; ks < 4; ks++) {
            uint32_t af[4][4];
#pragma unroll
            for (int mi = 0; mi < 4; mi++) {
                const uint32_t* p = Ab + (wm * 64 + mi * 16 + g) * APAD + ks * 8 + tg;
                af[mi][0] = p[0];
                af[mi][2] = p[4];
                af[mi][1] = p[8 * APAD];
                af[mi][3] = p[8 * APAD + 4];
            }
#pragma unroll
            for (int ni = 0; ni < 8; ni++) {
                const uint32_t* p = Bb + (wn * 64 + ni * 8 + g) * APAD + ks * 8 + tg;
                uint32_t b0 = p[0], b1 = p[4];
#pragma unroll
                for (int mi = 0; mi < 4; mi++)
                    mma8(acc[mi][ni], af[mi], b0, b1);
            }
        }
        __syncthreads();

        if (kt + 2 < 16) {
            uint32_t ad = sb + (AS_OFF(s) + r8 * APAD + c4) * 4;
            uint32_t bd = sb + (BS_OFF(s) + r8 * APAD + c4) * 4;
#pragma unroll
            for (int i = 0; i < 8; i++) {
                cp16(ad + i * 16 * APAD * 4, Abase + (kt + 2) * 32 + (size_t)i * 16 * 512);
                cp16(bd + i * 16 * APAD * 4, Bbase + (kt + 2) * 32 + (size_t)i * 16 * 512);
            }
            asm volatile("cp.async.commit_group;" ::: "memory");
        }
    }

#pragma unroll
    for (int mi = 0; mi < 4; mi++) {
        int row = m0 + wm * 64 + mi * 16 + g;
#pragma unroll
        for (int ni = 0; ni < 8; ni++) {
            int ncol = n0 + wn * 64 + ni * 8 + 2 * tg;
            int gcol = z * 512 + ncol;
            float b0 = bias[ncol], b1 = bias[ncol + 1];
            float2 v0 = make_float2(acc[mi][ni][0] + b0, acc[mi][ni][1] + b1);
            float2 v1 = make_float2(acc[mi][ni][2] + b0, acc[mi][ni][3] + b1);
            *(float2*)(Cout + (size_t)row * ldc + gcol) = v0;
            *(float2*)(Cout + (size_t)(row + 8) * ldc + gcol) = v1;
        }
    }
}

// ============================================================
// conversion kernels (fp32 -> tf32-rounded fp32 in global)
// ============================================================
__global__ void convert_x_kernel(const float* __restrict__ x, float* __restrict__ o)
{
    size_t i = (size_t)blockIdx.x * 256 + threadIdx.x;
    float4 v = ((const float4*)x)[i];
    ((uint4*)o)[i] = make_uint4(f2tf32(v.x), f2tf32(v.y), f2tf32(v.z), f2tf32(v.w));
}

__global__ void convert_w_kernel(const float* __restrict__ w0, const float* __restrict__ w1,
                                 const float* __restrict__ w2, const float* __restrict__ w3,
                                 float* __restrict__ o)
{
    size_t i = (size_t)blockIdx.x * 256 + threadIdx.x;
    const float* srcs[4] = {w0, w1, w2, w3};
#pragma unroll
    for (int m = 0; m < 4; m++) {
        float4 v = ((const float4*)srcs[m])[i];
        ((uint4*)(o + (size_t)m * 262144))[i] =
            make_uint4(f2tf32(v.x), f2tf32(v.y), f2tf32(v.z), f2tf32(v.w));
    }
}

// ============================================================
// Attention: flash-style online softmax, software-pipelined strips.
// One CTA per (b,h), 9 warps, warp owns 16 q-rows, 24-key strips.
// Q fragments loaded directly from global (no smem staging).
// Strip s+1's S-mmas issued before softmax(s) to overlap pipes.
// ============================================================
#define KP 36
#define VP 40
#define SP 36
#define ATT_SMEM_WORDS (2*144*KP + 144*VP + 9*16*SP)   // 21312 words = 85248 B

__device__ __forceinline__ void compute_strip(
    const uint32_t* __restrict__ ksh, const uint32_t* __restrict__ ksl,
    const uint32_t (&ah)[4][4], const uint32_t (&al)[4][4],
    int g, int tg, int s, float (&sacc)[3][4])
{
#pragma unroll
    for (int j = 0; j < 3; j++) {
#pragma unroll
        for (int r = 0; r < 4; r++) sacc[j][r] = 0.f;
        const int nt = 3 * s + j;
#pragma unroll
        for (int kt = 0; kt < 4; kt++) {
            const uint32_t* p = ksh + (nt * 8 + g) * KP + kt * 8 + tg;
            uint32_t bh0 = p[0], bh1 = p[4];
            const uint32_t* q = ksl + (nt * 8 + g) * KP + kt * 8 + tg;
            uint32_t bl0 = q[0], bl1 = q[4];
            mma8(sacc[j], ah[kt], bh0, bh1);
            mma8(sacc[j], al[kt], bh0, bh1);
            mma8(sacc[j], ah[kt], bl0, bl1);
        }
    }
}

__global__ void __launch_bounds__(288, 2)
attn_kernel(const float* __restrict__ mask,
            const float* __restrict__ logit_scale,
            float* __restrict__ attout)
{
    const int bh = blockIdx.x;
    const int b = bh >> 4;
    const int h = bh & 15;
    const int win = b & (NWIN - 1);

    const int tid = threadIdx.x;
    const int w = tid >> 5, lane = tid & 31;
    const int g = lane >> 2, tg = lane & 3;

    extern __shared__ uint32_t sm_u[];
    uint32_t* ksh = sm_u;                    // [144][KP]
    uint32_t* ksl = ksh + 144 * KP;          // [144][KP]
    uint32_t* vsm = ksl + 144 * KP;          // [144][VP]
    uint32_t* pstrip = vsm + 144 * VP;       // [9][16][SP]

    const float scale = expf(fminf(logit_scale[h], LOG100));

    const float* qbase = g_qkv + (size_t)(b * SEQ) * 1536 + h * 32;
    const float* kbase = qbase + 512;
    const float* vbase = qbase + 1024;

    // ---- load K (normalized, hi/lo split) and V (tf32), 2 threads/row ----
    {
        int r = tid >> 1, half = tid & 1;
        const float4* kr = (const float4*)(kbase + (size_t)r * 1536 + half * 16);
        float kv[16];
        float sq = 0.f;
#pragma unroll
        for (int i4 = 0; i4 < 4; i4++) {
            float4 f = kr[i4];
            kv[i4*4+0] = f.x; kv[i4*4+1] = f.y; kv[i4*4+2] = f.z; kv[i4*4+3] = f.w;
            sq += f.x*f.x + f.y*f.y + f.z*f.z + f.w*f.w;
        }
        sq += __shfl_xor_sync(0xffffffffu, sq, 1);
        float inv = 1.f / fmaxf(sqrtf(sq), 1e-12f);
#pragma unroll
        for (int i = 0; i < 16; i++) {
            int d = half * 16 + i;
            float f = kv[i] * inv;
            uint32_t hi = f2tf32(f);
            float lo = f - __uint_as_float(hi);
            ksh[r * KP + d] = hi;
            ksl[r * KP + d] = f2tf32(lo);
        }
        const float4* vr = (const float4*)(vbase + (size_t)r * 1536 + half * 16);
#pragma unroll
        for (int i4 = 0; i4 < 4; i4++) {
            float4 f = vr[i4];
            int d = half * 16 + i4 * 4;
            vsm[r * VP + d + 0] = f2tf32(f.x);
            vsm[r * VP + d + 1] = f2tf32(f.y);
            vsm[r * VP + d + 2] = f2tf32(f.z);
            vsm[r * VP + d + 3] = f2tf32(f.w);
        }
    }

    // ---- Q fragments directly from global (d = 4i + tg pattern) ----
    uint32_t ah[4][4], al[4][4];
    {
        const int r0 = w * 16 + g;
        const float* qr0 = qbase + (size_t)r0 * 1536 + tg;
        const float* qr1 = qr0 + (size_t)8 * 1536;
        float q0[8], q1[8];
        float sq0 = 0.f, sq1 = 0.f;
#pragma unroll
        for (int i = 0; i < 8; i++) {
            q0[i] = qr0[4 * i];
            q1[i] = qr1[4 * i];
            sq0 += q0[i] * q0[i];
            sq1 += q1[i] * q1[i];
        }
        sq0 += __shfl_xor_sync(0xffffffffu, sq0, 1);
        sq0 += __shfl_xor_sync(0xffffffffu, sq0, 2);
        sq1 += __shfl_xor_sync(0xffffffffu, sq1, 1);
        sq1 += __shfl_xor_sync(0xffffffffu, sq1, 2);
        float inv0 = scale / fmaxf(sqrtf(sq0), 1e-12f);
        float inv1 = scale / fmaxf(sqrtf(sq1), 1e-12f);
#pragma unroll
        for (int kt = 0; kt < 4; kt++) {
            float f;
            f = q0[2 * kt] * inv0;
            ah[kt][0] = f2tf32(f); al[kt][0] = f2tf32(f - __uint_as_float(ah[kt][0]));
            f = q0[2 * kt + 1] * inv0;
            ah[kt][2] = f2tf32(f); al[kt][2] = f2tf32(f - __uint_as_float(ah[kt][2]));
            f = q1[2 * kt] * inv1;
            ah[kt][1] = f2tf32(f); al[kt][1] = f2tf32(f - __uint_as_float(ah[kt][1]));
            f = q1[2 * kt + 1] * inv1;
            ah[kt][3] = f2tf32(f); al[kt][3] = f2tf32(f - __uint_as_float(ah[kt][3]));
        }
    }
    __syncthreads();   // K/V smem ready

    // ---- online softmax state ----
    const float NEG_INF = __int_as_float(0xff800000);
    float m0r = NEG_INF, m1r = NEG_INF;
    float s0r = 0.f, s1r = 0.f;
    float oc[4][4];
#pragma unroll
    for (int nt = 0; nt < 4; nt++)
#pragma unroll
        for (int r = 0; r < 4; r++) oc[nt][r] = 0.f;

    uint32_t* pw = pstrip + w * 16 * SP;
    const float* mrow = mask + (size_t)win * SEQ * SEQ
                      + (size_t)(w * 16 + g) * SEQ + 2 * tg;

    float sacc0[3][4], sacc1[3][4];
    compute_strip(ksh, ksl, ah, al, g, tg, 0, sacc0);

#pragma unroll
    for (int s = 0; s < 6; s++) {
        float (&cur)[3][4] = (s & 1) ? sacc1 : sacc0;
        float (&nxt)[3][4] = (s & 1) ? sacc0 : sacc1;

        // issue mask loads early
        float2 mk0[3], mk1[3];
#pragma unroll
        for (int j = 0; j < 3; j++) {
            int nt = 3 * s + j;
            mk0[j] = *(const float2*)(mrow + nt * 8);
            mk1[j] = *(const float2*)(mrow + 8 * SEQ + nt * 8);
        }

        // issue next strip's S-mmas (independent of softmax below)
        if (s < 5)
            compute_strip(ksh, ksl, ah, al, g, tg, s + 1, nxt);

        // softmax on current strip
        float mx0 = NEG_INF, mx1 = NEG_INF;
#pragma unroll
        for (int j = 0; j < 3; j++) {
            cur[j][0] += mk0[j].x; cur[j][1] += mk0[j].y;
            cur[j][2] += mk1[j].x; cur[j][3] += mk1[j].y;
            mx0 = fmaxf(mx0, fmaxf(cur[j][0], cur[j][1]));
            mx1 = fmaxf(mx1, fmaxf(cur[j][2], cur[j][3]));
        }
        mx0 = fmaxf(mx0, __shfl_xor_sync(0xffffffffu, mx0, 1));
        mx0 = fmaxf(mx0, __shfl_xor_sync(0xffffffffu, mx0, 2));
        mx1 = fmaxf(mx1, __shfl_xor_sync(0xffffffffu, mx1, 1));
        mx1 = fmaxf(mx1, __shfl_xor_sync(0xffffffffu, mx1, 2));

        float mn0 = fmaxf(m0r, mx0), mn1 = fmaxf(m1r, mx1);
        float f0 = __expf(m0r - mn0), f1 = __expf(m1r - mn1);
        m0r = mn0; m1r = mn1;
        s0r *= f0; s1r *= f1;
#pragma unroll
        for (int nt = 0; nt < 4; nt++) {
            oc[nt][0] *= f0; oc[nt][1] *= f0;
            oc[nt][2] *= f1; oc[nt][3] *= f1;
        }

#pragma unroll
        for (int j = 0; j < 3; j++) {
            float p0 = __expf(cur[j][0] - mn0);
            float p1 = __expf(cur[j][1] - mn0);
            float p2 = __expf(cur[j][2] - mn1);
            float p3 = __expf(cur[j][3] - mn1);
            s0r += p0 + p1;
            s1r += p2 + p3;
            uint32_t* d0 = pw + g * SP + j * 8 + 2 * tg;
            d0[0] = f2tf32(p0); d0[1] = f2tf32(p1);
            uint32_t* d1 = pw + (g + 8) * SP + j * 8 + 2 * tg;
            d1[0] = f2tf32(p2); d1[1] = f2tf32(p3);
        }
        __syncwarp();

        // PV: O += P_strip @ V[24 keys]
#pragma unroll
        for (int kt2 = 0; kt2 < 3; kt2++) {
            uint32_t a[4];
            const uint32_t* p = pw + g * SP + kt2 * 8 + tg;
            a[0] = p[0]; a[2] = p[4];
            const uint32_t* p2 = pw + (g + 8) * SP + kt2 * 8 + tg;
            a[1] = p2[0]; a[3] = p2[4];
            int key0 = s * 24 + kt2 * 8;
#pragma unroll
            for (int nt = 0; nt < 4; nt++) {
                uint32_t b0 = vsm[(key0 + tg) * VP + nt * 8 + g];
                uint32_t b1 = vsm[(key0 + tg + 4) * VP + nt * 8 + g];
                mma8(oc[nt], a, b0, b1);
            }
        }
        __syncwarp();
    }

    // ---- finalize ----
    s0r += __shfl_xor_sync(0xffffffffu, s0r, 1);
    s0r += __shfl_xor_sync(0xffffffffu, s0r, 2);
    s1r += __shfl_xor_sync(0xffffffffu, s1r, 1);
    s1r += __shfl_xor_sync(0xffffffffu, s1r, 2);
    float inv0 = 1.f / s0r, inv1 = 1.f / s1r;

    const int row0 = b * SEQ + w * 16 + g;
#pragma unroll
    for (int nt = 0; nt < 4; nt++) {
        int col = h * 32 + nt * 8 + 2 * tg;
        *(float2*)(attout + (size_t)row0 * 512 + col) =
            make_float2(rtf(oc[nt][0] * inv0), rtf(oc[nt][1] * inv0));
        *(float2*)(attout + (size_t)(row0 + 8) * 512 + col) =
            make_float2(rtf(oc[nt][2] * inv1), rtf(oc[nt][3] * inv1));
    }
}

// ============================================================
// launch
// ============================================================
extern "C" void kernel_launch(void* const* d_in, const int* in_sizes, int n_in,
                              void* d_out, int out_size)
{
    (void)in_sizes; (void)n_in; (void)out_size;
    const float* x    = (const float*)d_in[0];
    const float* mask = (const float*)d_in[1];
    const float* Wq   = (const float*)d_in[2];
    const float* bq   = (const float*)d_in[3];
    const float* Wk   = (const float*)d_in[4];
    const float* bk   = (const float*)d_in[5];
    const float* Wv   = (const float*)d_in[6];
    const float* bv   = (const float*)d_in[7];
    const float* Wp   = (const float*)d_in[8];
    const float* bp   = (const float*)d_in[9];
    const float* ls   = (const float*)d_in[10];
    float* out = (float*)d_out;

    void *qkv_p = nullptr, *att_p = nullptr, *xt_p = nullptr, *wt_p = nullptr;
    cudaGetSymbolAddress(&qkv_p, g_qkv);
    cudaGetSymbolAddress(&att_p, g_att);
    cudaGetSymbolAddress(&xt_p, g_xt);
    cudaGetSymbolAddress(&wt_p, g_wt);
    float* qkv = (float*)qkv_p;
    float* att = (float*)att_p;
    float* xt  = (float*)xt_p;
    float* wt  = (float*)wt_p;

    const int att_smem = ATT_SMEM_WORDS * 4;               // 85248 B
    cudaFuncSetAttribute(gemm_tf32_kernel,
                         cudaFuncAttributeMaxDynamicSharedMemorySize, GEMM_SMEM);
    cudaFuncSetAttribute(attn_kernel,
                         cudaFuncAttributeMaxDynamicSharedMemorySize, att_smem);

    // 0) round inputs to tf32 (in global)
    convert_x_kernel<<<MROWS * 512 / 4 / 256, 256>>>(x, xt);
    convert_w_kernel<<<256, 256>>>(Wq, Wk, Wv, Wp, wt);

    // 1) QKV projections: grid.x = 4 n-tiles * 3 z
    gemm_tf32_kernel<<<dim3(12, MROWS / 128), 128, GEMM_SMEM>>>(
        xt, wt, wt + 262144, wt + 2 * 262144, bq, bk, bv, qkv, 1536);

    // 2) attention (flash, software-pipelined strips)
    attn_kernel<<<BW * NH, 288, att_smem>>>(mask, ls, att);

    // 3) output projection
    gemm_tf32_kernel<<<dim3(4, MROWS / 128), 128, GEMM_SMEM>>>(
        att, wt + 3 * 262144, wt + 3 * 262144, wt + 3 * 262144, bp, bp, bp, out, 512);
}